// round 1
// baseline (speedup 1.0000x reference)
#include <cuda_runtime.h>
#include <math.h>

#define NQ   10001          // distinct quantized time values: floor(t/0.1), t in [0,1000)
#define NQP  10016          // padded to multiple of 32 (and of 4 for float4)
#define DD   1024
#define RR   256

// Scratch (device globals — no allocation allowed)
__device__ float g_redT[RR * NQP];      // reduced, transposed: [r][q]   (~10 MB)
__device__ float g_WeT[RR * DD];        // w_expand transposed: [r][d]   (1 MB)
__device__ float g_table[NQ * DD];      // encoding lookup table [q][d]  (~41 MB, L2-resident)

// ---------------------------------------------------------------------------
// Phase 0a: transpose w_expand (D,R) -> (R,D) for coalesced GEMM access
// grid: (DD) blocks x RR threads
__global__ void k_transpose_we(const float* __restrict__ we) {
    int d = blockIdx.x;
    int r = threadIdx.x;
    g_WeT[r * DD + d] = we[d * RR + r];   // read coalesced over r
}

// ---------------------------------------------------------------------------
// Phase 0b: reduced[r][q] = relu(cos(tq(q) * wr[r] + wrb[r]))
// cos computed in double of the fp32 argument: accurate regardless of fast-math.
// grid: (40, 256) = (q-chunks, r), 256 threads
__global__ void k_build_red(const float* __restrict__ wr,
                            const float* __restrict__ wrb) {
    int q = blockIdx.x * 256 + threadIdx.x;
    int r = blockIdx.y;
    if (q >= NQP) return;
    int qc = q < NQ ? q : (NQ - 1);       // clamp pad region (finite values, never stored)
    float tq  = (float)qc * 0.1f;         // matches floor(t/0.1f)*0.1f
    float arg = tq * wr[r] + wrb[r];      // fp32 argument like the reference
    float v   = (float)cos((double)arg);  // accurate cosine
    g_redT[r * NQP + q] = v > 0.0f ? v : 0.0f;
}

// ---------------------------------------------------------------------------
// Phase 1: table[q][d] = sum_r red[q][r] * WeT[r][d] + web[d]
// Tile per block: 32 q x 256 d, 256 threads, each thread: 16 q x 2 d accumulators.
// redT reads are warp-uniform (L1 broadcast, float4); WeT reads coalesced.
// grid: (313, 4)  [313*32 = 10016 = NQP exactly]
__global__ void __launch_bounds__(256) k_build_table(const float* __restrict__ web) {
    int t  = threadIdx.x;
    int dl = t & 127;
    int qg = t >> 7;                       // 0 or 1
    int qb = blockIdx.x * 32 + qg * 16;    // this thread's 16-q group (multiple of 16)
    int d1 = blockIdx.y * 256 + dl;
    int d2 = d1 + 128;

    float a1[16], a2[16];
#pragma unroll
    for (int i = 0; i < 16; ++i) { a1[i] = 0.0f; a2[i] = 0.0f; }

    const float4* redT4 = (const float4*)g_redT;

#pragma unroll 4
    for (int r = 0; r < RR; ++r) {
        float w1 = g_WeT[r * DD + d1];     // coalesced across warp
        float w2 = g_WeT[r * DD + d2];
        int base = (r * NQP + qb) >> 2;    // warp-uniform address -> broadcast
        float4 x0 = redT4[base + 0];
        float4 x1 = redT4[base + 1];
        float4 x2 = redT4[base + 2];
        float4 x3 = redT4[base + 3];
        float red[16] = { x0.x, x0.y, x0.z, x0.w,  x1.x, x1.y, x1.z, x1.w,
                          x2.x, x2.y, x2.z, x2.w,  x3.x, x3.y, x3.z, x3.w };
#pragma unroll
        for (int qi = 0; qi < 16; ++qi) {
            a1[qi] += red[qi] * w1;
            a2[qi] += red[qi] * w2;
        }
    }

    float b1 = web[d1];
    float b2 = web[d2];
#pragma unroll
    for (int qi = 0; qi < 16; ++qi) {
        int q = qb + qi;
        if (q < NQ) {
            g_table[q * DD + d1] = a1[qi] + b1;   // coalesced stores
            g_table[q * DD + d2] = a2[qi] + b2;
        }
    }
}

// ---------------------------------------------------------------------------
// Phase 2: out[b][:] = table[q(b)][:]
// One block per row; 256 threads x float4 = 1024 floats.
// __fdiv_rn: IEEE fp32 division (matches JAX boundary rounding even under fast-math).
// __stcs: streaming store — keep the table resident in L2, evict output first.
__global__ void __launch_bounds__(256) k_scatter(const float* __restrict__ tt,
                                                 float4* __restrict__ out) {
    int b = blockIdx.x;
    float tv = __ldg(tt + b);
    int q = (int)floorf(__fdiv_rn(tv, 0.1f));
    q = max(0, min(q, NQ - 1));
    const float4* row = (const float4*)(g_table + (size_t)q * DD);
    float4 v = row[threadIdx.x];
    __stcs(out + (size_t)b * (DD / 4) + threadIdx.x, v);
}

// ---------------------------------------------------------------------------
extern "C" void kernel_launch(void* const* d_in, const int* in_sizes, int n_in,
                              void* d_out, int out_size) {
    const float* t   = (const float*)d_in[0];   // (B,)
    const float* wr  = (const float*)d_in[1];   // (R,1)
    const float* wrb = (const float*)d_in[2];   // (R,)
    const float* we  = (const float*)d_in[3];   // (D,R)
    const float* web = (const float*)d_in[4];   // (D,)
    float* out = (float*)d_out;
    int B = in_sizes[0];

    k_transpose_we<<<DD, RR>>>(we);
    k_build_red<<<dim3((NQP + 255) / 256, RR), 256>>>(wr, wrb);
    k_build_table<<<dim3(NQP / 32, DD / 256), 256>>>(web);
    k_scatter<<<B, 256>>>(t, (float4*)out);
}

// round 2
// speedup vs baseline: 1.0334x; 1.0334x over previous
#include <cuda_runtime.h>
#include <math.h>

#define NQ   10001          // distinct quantized time values: floor(t/0.1), t in [0,1000)
#define NQP  10016          // padded to multiple of 32 (and of 4 for float4)
#define DD   1024
#define RR   256
#define ROWS_PER_BLK 8      // scatter rows per block (B=262144 divisible by 8)

// Scratch (device globals — no allocation allowed)
__device__ float g_redT[RR * NQP];      // reduced, transposed: [r][q]   (~10 MB)
__device__ float g_WeT[RR * DD];        // w_expand transposed: [r][d]   (1 MB)
__device__ float g_table[NQ * DD];      // encoding lookup table [q][d]  (~41 MB, L2-resident)

// ---------------------------------------------------------------------------
// Packed fp32x2 helpers (sm_103a FFMA2: 2x fp32 FLOP per instruction, IEEE per lane)
__device__ __forceinline__ void fma_f32x2(unsigned long long& d,
                                          unsigned long long a,
                                          unsigned long long b) {
    asm("fma.rn.f32x2 %0, %1, %2, %0;" : "+l"(d) : "l"(a), "l"(b));
}
__device__ __forceinline__ unsigned long long splat_f32(float w) {
    unsigned long long r;
    asm("mov.b64 %0, {%1, %1};" : "=l"(r) : "f"(w));
    return r;
}

// ---------------------------------------------------------------------------
// Phase 0a: transpose w_expand (D,R) -> (R,D) for coalesced GEMM access
__global__ void k_transpose_we(const float* __restrict__ we) {
    int d = blockIdx.x;
    int r = threadIdx.x;
    g_WeT[r * DD + d] = we[d * RR + r];   // read coalesced over r
}

// ---------------------------------------------------------------------------
// Phase 0b: reduced[r][q] = relu(cos(tq(q) * wr[r] + wrb[r]))
// fp32 Cody-Waite range reduction (|arg| <= ~153, k <= 25) + cosf on |r|<=pi.
// Accurate to ~1e-6 with or without fast-math; avoids the slow FP64 pipe.
__global__ void k_build_red(const float* __restrict__ wr,
                            const float* __restrict__ wrb) {
    int q = blockIdx.x * 256 + threadIdx.x;
    int r = blockIdx.y;
    if (q >= NQP) return;
    int qc = q < NQ ? q : (NQ - 1);       // clamp pad region (finite, never consumed)
    float tq  = (float)qc * 0.1f;         // matches floor(t/0.1f)*0.1f
    float arg = tq * wr[r] + wrb[r];      // fp32 argument like the reference
    // two-term 2*pi split: 6.28125 exact in 9 mantissa bits
    float k   = rintf(arg * 0.15915494309189535f);      // arg / (2*pi)
    float red = fmaf(-k, 6.28125f, arg);                 // fma-exact cancellation
    red       = fmaf(-k, 1.9353071795864769e-3f, red);   // low word of 2*pi
    float v   = cosf(red);
    g_redT[r * NQP + q] = v > 0.0f ? v : 0.0f;
}

// ---------------------------------------------------------------------------
// Phase 1: table[q][d] = sum_r red[q][r] * WeT[r][d] + web[d]
// Block tile: 32 q x 256 d, 256 threads; each thread: 8 q-PAIRS x 2 d via FFMA2.
// redT float4 loads reinterpret directly as packed (q,q+1) b64 operands — no packs.
// grid: (313, 4)  [313*32 = 10016 = NQP exactly]
__global__ void __launch_bounds__(256) k_build_table(const float* __restrict__ web) {
    int t  = threadIdx.x;
    int dl = t & 127;
    int qg = t >> 7;                       // 0 or 1
    int qb = blockIdx.x * 32 + qg * 16;    // this thread's 16-q group
    int d1 = blockIdx.y * 256 + dl;
    int d2 = d1 + 128;

    unsigned long long a1[8], a2[8];       // packed (q even, q odd) accumulators
#pragma unroll
    for (int i = 0; i < 8; ++i) { a1[i] = 0ULL; a2[i] = 0ULL; }

    const ulonglong2* redT2 = (const ulonglong2*)g_redT;  // 16B = two f32 pairs

#pragma unroll 4
    for (int r = 0; r < RR; ++r) {
        unsigned long long w1p = splat_f32(g_WeT[r * DD + d1]);  // coalesced
        unsigned long long w2p = splat_f32(g_WeT[r * DD + d2]);
        int base = (r * NQP + qb) >> 2;    // warp-uniform -> L1 broadcast
        ulonglong2 y0 = redT2[base + 0];   // (q0,q1),(q2,q3)
        ulonglong2 y1 = redT2[base + 1];
        ulonglong2 y2 = redT2[base + 2];
        ulonglong2 y3 = redT2[base + 3];
        unsigned long long rp[8] = { y0.x, y0.y, y1.x, y1.y,
                                     y2.x, y2.y, y3.x, y3.y };
#pragma unroll
        for (int p = 0; p < 8; ++p) {
            fma_f32x2(a1[p], rp[p], w1p);
            fma_f32x2(a2[p], rp[p], w2p);
        }
    }

    float b1 = web[d1];
    float b2 = web[d2];
#pragma unroll
    for (int p = 0; p < 8; ++p) {
        unsigned int lo1 = (unsigned int)(a1[p]);
        unsigned int hi1 = (unsigned int)(a1[p] >> 32);
        unsigned int lo2 = (unsigned int)(a2[p]);
        unsigned int hi2 = (unsigned int)(a2[p] >> 32);
        int q0 = qb + 2 * p;
        int q1 = q0 + 1;
        if (q0 < NQ) {
            g_table[(size_t)q0 * DD + d1] = __uint_as_float(lo1) + b1;
            g_table[(size_t)q0 * DD + d2] = __uint_as_float(lo2) + b2;
        }
        if (q1 < NQ) {
            g_table[(size_t)q1 * DD + d1] = __uint_as_float(hi1) + b1;
            g_table[(size_t)q1 * DD + d2] = __uint_as_float(hi2) + b2;
        }
    }
}

// ---------------------------------------------------------------------------
// Phase 2: out[b][:] = table[q(b)][:]
// 8 rows per block, 256 threads; each thread: 8 independent LDG.128 (MLP=8)
// then 8 STG.128. __fdiv_rn: IEEE fp32 division under any fast-math setting.
// __stcs streaming stores keep the table L2-resident.
__global__ void __launch_bounds__(256) k_scatter(const float* __restrict__ tt,
                                                 float4* __restrict__ out) {
    __shared__ int qidx[ROWS_PER_BLK];
    int b0 = blockIdx.x * ROWS_PER_BLK;
    if (threadIdx.x < ROWS_PER_BLK) {
        float tv = __ldg(tt + b0 + threadIdx.x);
        int q = (int)floorf(__fdiv_rn(tv, 0.1f));
        qidx[threadIdx.x] = max(0, min(q, NQ - 1));
    }
    __syncthreads();

    const float4* tab = (const float4*)g_table;
    float4 v[ROWS_PER_BLK];
#pragma unroll
    for (int i = 0; i < ROWS_PER_BLK; ++i)
        v[i] = tab[(size_t)qidx[i] * (DD / 4) + threadIdx.x];
#pragma unroll
    for (int i = 0; i < ROWS_PER_BLK; ++i)
        __stcs(out + ((size_t)(b0 + i) * (DD / 4) + threadIdx.x), v[i]);
}

// ---------------------------------------------------------------------------
extern "C" void kernel_launch(void* const* d_in, const int* in_sizes, int n_in,
                              void* d_out, int out_size) {
    const float* t   = (const float*)d_in[0];   // (B,)
    const float* wr  = (const float*)d_in[1];   // (R,1)
    const float* wrb = (const float*)d_in[2];   // (R,)
    const float* we  = (const float*)d_in[3];   // (D,R)
    const float* web = (const float*)d_in[4];   // (D,)
    float* out = (float*)d_out;
    int B = in_sizes[0];

    k_transpose_we<<<DD, RR>>>(we);
    k_build_red<<<dim3((NQP + 255) / 256, RR), 256>>>(wr, wrb);
    k_build_table<<<dim3(NQP / 32, DD / 256), 256>>>(web);
    k_scatter<<<B / ROWS_PER_BLK, 256>>>(t, (float4*)out);
}

// round 3
// speedup vs baseline: 1.7903x; 1.7324x over previous
#include <cuda_runtime.h>
#include <math.h>

#define NQ   10001          // distinct quantized times: floor(t/0.1), t in [0,1000)
#define NQP  10016          // padded to multiple of 32
#define DD   1024
#define RR   256
#define ROWS_PER_BLK 8      // scatter rows per block

// Scratch (device globals — no allocation allowed)
__device__ float g_WeT[RR * DD];        // w_expand transposed [r][d]   (1 MB)
__device__ float g_table[NQ * DD];      // encoding LUT [q][d]          (~41 MB, L2-resident)

// ---------------------------------------------------------------------------
// Packed fp32x2 helpers (sm_103a FFMA2)
__device__ __forceinline__ void fma_f32x2(unsigned long long& d,
                                          unsigned long long a,
                                          unsigned long long b) {
    asm("fma.rn.f32x2 %0, %1, %2, %0;" : "+l"(d) : "l"(a), "l"(b));
}
__device__ __forceinline__ unsigned long long splat_f32(float w) {
    unsigned long long r;
    asm("mov.b64 %0, {%1, %1};" : "=l"(r) : "f"(w));
    return r;
}
__device__ __forceinline__ float lo_f(unsigned long long p) {
    return __uint_as_float((unsigned int)p);
}
__device__ __forceinline__ float hi_f(unsigned long long p) {
    return __uint_as_float((unsigned int)(p >> 32));
}

// ---------------------------------------------------------------------------
// Phase 0: tiled transpose w_expand (D,R) -> (R,D); coalesced both sides.
// grid (RR/32, DD/32) = (8, 32), block (32, 8)
__global__ void k_transpose_we(const float* __restrict__ we) {
    __shared__ float tile[32][33];
    int tx = threadIdx.x, ty = threadIdx.y;
    int r0 = blockIdx.x * 32, d0 = blockIdx.y * 32;
#pragma unroll
    for (int k = 0; k < 32; k += 8)
        tile[ty + k][tx] = we[(d0 + ty + k) * RR + (r0 + tx)];
    __syncthreads();
#pragma unroll
    for (int k = 0; k < 32; k += 8)
        g_WeT[(r0 + ty + k) * DD + (d0 + tx)] = tile[tx][ty + k];
}

// ---------------------------------------------------------------------------
// Phase 1 (fused): per block, compute red[r][q]=relu(cos(tq*wr+wrb)) tile in
// smem, then table[q][d] = sum_r red * WeT + web via FFMA2.
// Block: 256 threads. Tile: 32 q x 256 d. Thread: 4 q-pairs x 4 d.
// grid (NQP/32 = 313, DD/256 = 4)
__global__ void __launch_bounds__(256) k_build_table(const float* __restrict__ wr,
                                                     const float* __restrict__ wrb,
                                                     const float* __restrict__ web) {
    __shared__ float sRed[RR * 32];   // [r][q_local], 32 KB
    __shared__ float sWr[RR], sWrb[RR];

    int tid = threadIdx.x;
    int qb0 = blockIdx.x * 32;

    // stage reduce weights
    if (tid < RR) { sWr[tid] = wr[tid]; sWrb[tid] = wrb[tid]; }
    __syncthreads();

    // fill red tile: 8192 elems / 256 threads = 32 iters
#pragma unroll 4
    for (int i = tid; i < RR * 32; i += 256) {
        int r  = i >> 5;
        int ql = i & 31;
        int qc = min(qb0 + ql, NQ - 1);           // pad region clamped (never stored)
        float tq  = (float)qc * 0.1f;             // matches floor(t/0.1f)*0.1f
        float arg = fmaf(tq, sWr[r], sWrb[r]);
        // Cody-Waite 2*pi reduction (|arg| <= ~153): exact under fast-math
        float k   = rintf(arg * 0.15915494309189535f);
        float red = fmaf(-k, 6.28125f, arg);
        red       = fmaf(-k, 1.9353071795864769e-3f, red);
        float v   = cosf(red);
        sRed[r * 32 + ql] = v > 0.0f ? v : 0.0f;
    }
    __syncthreads();

    // GEMM: thread -> 4 consecutive d, 8 q (4 packed pairs)
    int dt = tid & 63;                 // 64 d-threads
    int qg = tid >> 6;                 // 4 q-groups of 8
    int db = blockIdx.y * 256 + dt * 4;

    unsigned long long acc[4][4];      // [pair][dj]
#pragma unroll
    for (int p = 0; p < 4; ++p)
#pragma unroll
        for (int j = 0; j < 4; ++j) acc[p][j] = 0ULL;

    const float4* WeT4 = (const float4*)g_WeT;
    const ulonglong2* sRed2 = (const ulonglong2*)sRed;

#pragma unroll 4
    for (int r = 0; r < RR; ++r) {
        float4 w = WeT4[(r * DD + db) >> 2];          // coalesced LDG.128
        unsigned long long wp[4] = { splat_f32(w.x), splat_f32(w.y),
                                     splat_f32(w.z), splat_f32(w.w) };
        int sb = (r * 32 + qg * 8) >> 2;              // warp-uniform -> broadcast
        ulonglong2 y0 = sRed2[sb];                    // pairs (q0,q1),(q2,q3)
        ulonglong2 y1 = sRed2[sb + 1];                // pairs (q4,q5),(q6,q7)
        unsigned long long rp[4] = { y0.x, y0.y, y1.x, y1.y };
#pragma unroll
        for (int p = 0; p < 4; ++p)
#pragma unroll
            for (int j = 0; j < 4; ++j)
                fma_f32x2(acc[p][j], rp[p], wp[j]);
    }

    float4 b = ((const float4*)web)[db >> 2];
#pragma unroll
    for (int p = 0; p < 4; ++p) {
        int q0 = qb0 + qg * 8 + 2 * p;
        if (q0 < NQ) {
            float4 o;
            o.x = lo_f(acc[p][0]) + b.x;  o.y = lo_f(acc[p][1]) + b.y;
            o.z = lo_f(acc[p][2]) + b.z;  o.w = lo_f(acc[p][3]) + b.w;
            ((float4*)g_table)[((size_t)q0 * DD + db) >> 2] = o;   // coalesced STG.128
        }
        if (q0 + 1 < NQ) {
            float4 o;
            o.x = hi_f(acc[p][0]) + b.x;  o.y = hi_f(acc[p][1]) + b.y;
            o.z = hi_f(acc[p][2]) + b.z;  o.w = hi_f(acc[p][3]) + b.w;
            ((float4*)g_table)[((size_t)(q0 + 1) * DD + db) >> 2] = o;
        }
    }
}

// ---------------------------------------------------------------------------
// Phase 2: out[b][:] = table[q(b)][:]
// 8 rows/block, 256 threads; 8 independent LDG.128 then 8 STG.128 (streaming).
__global__ void __launch_bounds__(256) k_scatter(const float* __restrict__ tt,
                                                 float4* __restrict__ out) {
    __shared__ int qidx[ROWS_PER_BLK];
    int b0 = blockIdx.x * ROWS_PER_BLK;
    if (threadIdx.x < ROWS_PER_BLK) {
        float tv = __ldg(tt + b0 + threadIdx.x);
        int q = (int)floorf(__fdiv_rn(tv, 0.1f));   // IEEE div under any fast-math
        qidx[threadIdx.x] = max(0, min(q, NQ - 1));
    }
    __syncthreads();

    const float4* tab = (const float4*)g_table;
    float4 v[ROWS_PER_BLK];
#pragma unroll
    for (int i = 0; i < ROWS_PER_BLK; ++i)
        v[i] = tab[(size_t)qidx[i] * (DD / 4) + threadIdx.x];
#pragma unroll
    for (int i = 0; i < ROWS_PER_BLK; ++i)
        __stcs(out + ((size_t)(b0 + i) * (DD / 4) + threadIdx.x), v[i]);
}

// ---------------------------------------------------------------------------
extern "C" void kernel_launch(void* const* d_in, const int* in_sizes, int n_in,
                              void* d_out, int out_size) {
    const float* t   = (const float*)d_in[0];   // (B,)
    const float* wr  = (const float*)d_in[1];   // (R,1)
    const float* wrb = (const float*)d_in[2];   // (R,)
    const float* we  = (const float*)d_in[3];   // (D,R)
    const float* web = (const float*)d_in[4];   // (D,)
    float* out = (float*)d_out;
    int B = in_sizes[0];

    k_transpose_we<<<dim3(RR / 32, DD / 32), dim3(32, 8)>>>(we);
    k_build_table<<<dim3(NQP / 32, DD / 256), 256>>>(wr, wrb, web);
    k_scatter<<<B / ROWS_PER_BLK, 256>>>(t, (float4*)out);
}